// round 1
// baseline (speedup 1.0000x reference)
#include <cuda_runtime.h>
#include <cuda_bf16.h>

// Problem constants (fixed by the reference)
#define BB 2
#define CC 64
#define HH 512
#define WW 512
#define HW (HH * WW)          // 262144
#define NN 4096
#define KK 5
#define NPAIR (BB * NN)       // 8192
// max_distance = sqrt(512^2 + 512^2); NON_MATCH_WEIGHT/K cancels to 1
#define INV_MAXDIST (1.0f / 724.07733f)
#define FEAT_THRESH_NOMATCH 16.0f
#define FINAL_SCALE (1.0f / ((KK + 1.0f) * NN))   // 1/24576

// Scratch (allocation-free rule: __device__ globals)
__device__ float g_fo[NPAIR * CC];     // compacted other-features per match [b][i][c]
__device__ float g_partial[NPAIR];     // per-match loss partial

// ---------------------------------------------------------------------------
// Kernel A: gather inputs_other features at lin_oth into compact [B,N,C]
// One thread per (b,i,c). Reads strided (inherent), writes coalesced.
// ---------------------------------------------------------------------------
__global__ void gather_fo_kernel(const float* __restrict__ oth,
                                 const int* __restrict__ inds_other) {
    int tid = blockIdx.x * blockDim.x + threadIdx.x;   // 0 .. B*N*C-1
    if (tid >= NPAIR * CC) return;
    int c  = tid & (CC - 1);
    int bi = tid >> 6;            // b*N + i
    int b  = bi >> 12;            // /4096
    int i  = bi & (NN - 1);
    int x  = inds_other[b * 2 * NN + i];
    int y  = inds_other[b * 2 * NN + NN + i];
    int lin = HH * y + x;
    g_fo[tid] = oth[(size_t)(b * CC + c) * HW + lin];
}

// ---------------------------------------------------------------------------
// Kernel B: one warp per match pair. Each lane owns 2 channels.
// fr read strided (once), fo[i] and fo[j_k] read coalesced from g_fo.
// ---------------------------------------------------------------------------
__global__ void match_kernel(const float* __restrict__ ref,
                             const float* __restrict__ weights,
                             const int* __restrict__ inds_ref,
                             const int* __restrict__ rand_inds) {
    int gwarp = (blockIdx.x * blockDim.x + threadIdx.x) >> 5;
    int lane  = threadIdx.x & 31;
    if (gwarp >= NPAIR) return;
    int b = gwarp >> 12;
    int i = gwarp & (NN - 1);

    // lin index of the reference point
    int xr = inds_ref[b * 2 * NN + i];
    int yr = inds_ref[b * 2 * NN + NN + i];
    int linr = HH * yr + xr;

    // fr: two strided channel loads per lane
    const float* refp = ref + (size_t)b * CC * HW + linr;
    int c0 = 2 * lane;
    float fr0 = refp[(size_t)c0 * HW];
    float fr1 = refp[(size_t)(c0 + 1) * HW];

    // fo[i]: coalesced float2
    const float2* fo_i = reinterpret_cast<const float2*>(g_fo + (size_t)gwarp * CC);
    float2 fo = fo_i[lane];
    float d0 = fr0 - fo.x, d1 = fr1 - fo.y;
    float sm = d0 * d0 + d1 * d1;

    // negatives
    int   jarr[KK];
    float sk[KK];
    const int* ri = rand_inds + (size_t)gwarp * KK;
#pragma unroll
    for (int k = 0; k < KK; k++) {
        int j = ri[k];                     // uniform across the warp
        jarr[k] = j;
        const float2* fo_j =
            reinterpret_cast<const float2*>(g_fo + (size_t)(b * NN + j) * CC);
        float2 fj = fo_j[lane];
        float e0 = fr0 - fj.x, e1 = fr1 - fj.y;
        sk[k] = e0 * e0 + e1 * e1;
    }

    // warp reduction of 6 sums
#pragma unroll
    for (int off = 16; off > 0; off >>= 1) {
        sm += __shfl_down_sync(0xFFFFFFFFu, sm, off);
#pragma unroll
        for (int k = 0; k < KK; k++)
            sk[k] += __shfl_down_sync(0xFFFFFFFFu, sk[k], off);
    }

    if (lane == 0) {
        float total = weights[b * NN + i] * fmaxf(sm, 0.0f);
#pragma unroll
        for (int k = 0; k < KK; k++) {
            int j  = jarr[k];
            float xj = (float)inds_ref[b * 2 * NN + j];
            float yj = (float)inds_ref[b * 2 * NN + NN + j];
            float dx = (float)xr - xj;
            float dy = (float)yr - yj;
            float dist = sqrtf(dx * dx + dy * dy);
            total += (-dist * INV_MAXDIST) * fminf(sk[k], FEAT_THRESH_NOMATCH);
        }
        g_partial[gwarp] = total * FINAL_SCALE;
    }
}

// ---------------------------------------------------------------------------
// Kernel C: deterministic single-block reduction of the 8192 partials.
// ---------------------------------------------------------------------------
__global__ void reduce_kernel(float* __restrict__ out) {
    __shared__ float s[256];
    float acc = 0.0f;
    for (int idx = threadIdx.x; idx < NPAIR; idx += 256)
        acc += g_partial[idx];
    s[threadIdx.x] = acc;
    __syncthreads();
#pragma unroll
    for (int stride = 128; stride > 0; stride >>= 1) {
        if (threadIdx.x < stride) s[threadIdx.x] += s[threadIdx.x + stride];
        __syncthreads();
    }
    if (threadIdx.x == 0) out[0] = s[0];
}

extern "C" void kernel_launch(void* const* d_in, const int* in_sizes, int n_in,
                              void* d_out, int out_size) {
    const float* inputs_ref   = (const float*)d_in[0];
    const float* inputs_other = (const float*)d_in[1];
    const float* weights      = (const float*)d_in[2];
    const int*   inds_ref     = (const int*)d_in[3];
    const int*   inds_other   = (const int*)d_in[4];
    const int*   rand_inds    = (const int*)d_in[5];
    float* out = (float*)d_out;

    // A: B*N*C threads
    gather_fo_kernel<<<(NPAIR * CC + 255) / 256, 256>>>(inputs_other, inds_other);
    // B: one warp per pair -> NPAIR*32 threads
    match_kernel<<<(NPAIR * 32 + 255) / 256, 256>>>(inputs_ref, weights,
                                                    inds_ref, rand_inds);
    // C: single block, deterministic
    reduce_kernel<<<1, 256>>>(out);
}